// round 11
// baseline (speedup 1.0000x reference)
#include <cuda_runtime.h>
#include <cuda_fp16.h>
#include <math.h>
#include <stdint.h>

#define En     200000
#define Pn     50000
#define Dn     128
#define NNZn   2000000
#define Cn     32
#define NSEEDn 320
#define G3     384   // 3*D

// ---------------- scratch (device globals; no allocation allowed) ----------------
__device__ uint2 d_pmsgH[(size_t)Pn * 32];   // fp16 msg (4 halves per uint2)
__device__ uint2 d_emsgH[(size_t)En * 32];
__device__ uint2 d_psH[(size_t)Pn * 32];     // fp16 copy of ps (gather source)
__device__ float d_esB[(size_t)En * Dn];     // ping-pong for es
__device__ float d_psB[(size_t)Pn * Dn];     // ping-pong for ps
__device__ int   d_cntP[Pn];
__device__ int   d_offP[Pn + 1];
__device__ int   d_curP[Pn];
__device__ int   d_cntE[En];
__device__ int   d_offE[En + 1];
__device__ int   d_curE[En];
__device__ int2  d_eiP[NNZn];
__device__ int2  d_eiE[NNZn];
__device__ float d_smean[Dn];
__device__ int   d_partP[64];
__device__ int   d_partE[256];
// fp16 gate-grouped cat weights, 4 slots (l0_p, l0_e, l1_p, l1_e)
__device__ uint32_t d_wcat3[4 * 512 * 128];

#define NBP ((Pn + 1023) / 1024)   // 49
#define NBE ((En + 1023) / 1024)   // 196

// ---------------- helpers ----------------
__device__ __forceinline__ uint32_t smem_u32(const void* p) {
    uint32_t a;
    asm("{ .reg .u64 t; cvta.to.shared.u64 t, %1; cvt.u32.u64 %0, t; }" : "=r"(a) : "l"(p));
    return a;
}
__device__ __forceinline__ float sigmf(float x) { return 1.f / (1.f + expf(-x)); }
__device__ __forceinline__ uint32_t pack_h2(float a, float b) {
    __half2 h = __floats2half2_rn(a, b);
    return *(uint32_t*)&h;
}
__device__ __forceinline__ uint2 pack_f4(float4 v) {
    uint2 o;
    o.x = pack_h2(v.x, v.y);
    o.y = pack_h2(v.z, v.w);
    return o;
}

#define MMA_F16(acc, a0, a1, a2, a3, b0, b1)                                \
    asm volatile("mma.sync.aligned.m16n8k16.row.col.f32.f16.f16.f32 "       \
                 "{%0,%1,%2,%3}, {%4,%5,%6,%7}, {%8,%9}, {%0,%1,%2,%3};"    \
                 : "+f"(acc[0]), "+f"(acc[1]), "+f"(acc[2]), "+f"(acc[3])   \
                 : "r"(a0), "r"(a1), "r"(a2), "r"(a3), "r"(b0), "r"(b1));

// ---------------- CSR build ----------------
__global__ void k_zero_counts() {
    int i = blockIdx.x * blockDim.x + threadIdx.x;
    if (i < En) d_cntE[i] = 0;
    if (i < Pn) d_cntP[i] = 0;
}

__global__ void k_count(const int* __restrict__ rows, const int* __restrict__ cols) {
    int i = blockIdx.x * blockDim.x + threadIdx.x;
    if (i < NNZn) {
        atomicAdd(&d_cntE[rows[i]], 1);
        atomicAdd(&d_cntP[cols[i]], 1);
    }
}

__global__ void k_scan1() {
    __shared__ int s[1024];
    int isE = (blockIdx.x >= NBP);
    int b = isE ? blockIdx.x - NBP : blockIdx.x;
    const int* cnt = isE ? d_cntE : d_cntP;
    int* off = isE ? d_offE : d_offP;
    int* part = isE ? d_partE : d_partP;
    int n = isE ? En : Pn;
    int g = b * 1024 + threadIdx.x;
    s[threadIdx.x] = (g < n) ? cnt[g] : 0;
    __syncthreads();
    for (int o = 1; o < 1024; o <<= 1) {
        int t = (threadIdx.x >= o) ? s[threadIdx.x - o] : 0;
        __syncthreads();
        s[threadIdx.x] += t;
        __syncthreads();
    }
    if (g < n) off[g + 1] = s[threadIdx.x];
    if (threadIdx.x == 1023) part[b] = s[1023];
    if (g == 0) off[0] = 0;
}

__global__ void k_scan2() {
    __shared__ int s[1024];
    int isE = (blockIdx.x == 1);
    int* part = isE ? d_partE : d_partP;
    int n = isE ? NBE : NBP;
    s[threadIdx.x] = (threadIdx.x < n) ? part[threadIdx.x] : 0;
    __syncthreads();
    for (int o = 1; o < 1024; o <<= 1) {
        int t = (threadIdx.x >= o) ? s[threadIdx.x - o] : 0;
        __syncthreads();
        s[threadIdx.x] += t;
        __syncthreads();
    }
    if (threadIdx.x < n)
        part[threadIdx.x] = (threadIdx.x == 0) ? 0 : s[threadIdx.x - 1];
}

__global__ void k_scan3() {
    int isE = (blockIdx.x >= NBP);
    int b = isE ? blockIdx.x - NBP : blockIdx.x;
    int* off = isE ? d_offE : d_offP;
    int* cur = isE ? d_curE : d_curP;
    const int* part = isE ? d_partE : d_partP;
    int n = isE ? En : Pn;
    int g = b * 1024 + threadIdx.x;
    if (g < n) {
        int v = off[g + 1] + part[b];
        off[g + 1] = v;
        if (g + 1 < n) cur[g + 1] = v;
    }
    if (g == 0) cur[0] = 0;
}

__global__ void k_fill(const int* __restrict__ rows, const int* __restrict__ cols,
                       const float* __restrict__ vals) {
    int i = blockIdx.x * blockDim.x + threadIdx.x;
    if (i < NNZn) {
        int r = rows[i], c = cols[i];
        int vb = __float_as_int(vals[i]);
        int pp = atomicAdd(&d_curP[c], 1);
        d_eiP[pp] = make_int2(r, vb);
        int pe = atomicAdd(&d_curE[r], 1);
        d_eiE[pe] = make_int2(c, vb);
    }
}

// ---------------- seed mean ----------------
__global__ void k_seed_mean(const float* __restrict__ es, const int* __restrict__ sidx) {
    __shared__ float red[8][128];
    int d = threadIdx.x, ty = threadIdx.y;
    float s = 0.f;
    for (int i = ty; i < NSEEDn; i += 8)
        s += es[(size_t)sidx[i] * Dn + d];
    red[ty][d] = s;
    __syncthreads();
    if (ty == 0) {
        float tot = 0.f;
        #pragma unroll
        for (int j = 0; j < 8; j++) tot += red[j][d];
        d_smean[d] = tot * (1.f / NSEEDn);
    }
}

// ---------------- SpMM P-side: fp32 gather (es), fp16 msg out ----------------
__global__ void k_spmm_f32(const float4* __restrict__ src, uint2* __restrict__ dstH,
                           const int* __restrict__ off, const int2* __restrict__ ei,
                           int nseg) {
    int seg = blockIdx.x * 8 + threadIdx.y;
    if (seg >= nseg) return;
    int lane = threadIdx.x;
    float4 acc = make_float4(0.f, 0.f, 0.f, 0.f);
    int b = off[seg], e = off[seg + 1];
    int t = b;
    for (; t + 4 <= e; t += 4) {
        int2 e0 = ei[t], e1 = ei[t + 1], e2 = ei[t + 2], e3 = ei[t + 3];
        float4 x0 = src[(size_t)e0.x * 32 + lane];
        float4 x1 = src[(size_t)e1.x * 32 + lane];
        float4 x2 = src[(size_t)e2.x * 32 + lane];
        float4 x3 = src[(size_t)e3.x * 32 + lane];
        float v0 = __int_as_float(e0.y), v1 = __int_as_float(e1.y);
        float v2 = __int_as_float(e2.y), v3 = __int_as_float(e3.y);
        acc.x += x0.x * v0 + x1.x * v1 + x2.x * v2 + x3.x * v3;
        acc.y += x0.y * v0 + x1.y * v1 + x2.y * v2 + x3.y * v3;
        acc.z += x0.z * v0 + x1.z * v1 + x2.z * v2 + x3.z * v3;
        acc.w += x0.w * v0 + x1.w * v1 + x2.w * v2 + x3.w * v3;
    }
    for (; t < e; t++) {
        int2 e0 = ei[t];
        float v0 = __int_as_float(e0.y);
        float4 x0 = src[(size_t)e0.x * 32 + lane];
        acc.x += x0.x * v0; acc.y += x0.y * v0;
        acc.z += x0.z * v0; acc.w += x0.w * v0;
    }
    dstH[(size_t)seg * 32 + lane] = pack_f4(acc);
}

// ---------------- SpMM E-side: fp16 gather (psH), +smean, fp16 msg out ----------------
__global__ void k_spmm_h16(const uint2* __restrict__ srcH, uint2* __restrict__ dstH,
                           const int* __restrict__ off, const int2* __restrict__ ei,
                           int nseg) {
    int seg = blockIdx.x * 8 + threadIdx.y;
    if (seg >= nseg) return;
    int lane = threadIdx.x;
    float4 acc = ((const float4*)d_smean)[lane];
    int b = off[seg], e = off[seg + 1];
    int t = b;
    for (; t + 4 <= e; t += 4) {
        int2 e0 = ei[t], e1 = ei[t + 1], e2 = ei[t + 2], e3 = ei[t + 3];
        uint2 u0 = srcH[(size_t)e0.x * 32 + lane];
        uint2 u1 = srcH[(size_t)e1.x * 32 + lane];
        uint2 u2 = srcH[(size_t)e2.x * 32 + lane];
        uint2 u3 = srcH[(size_t)e3.x * 32 + lane];
        float v0 = __int_as_float(e0.y), v1 = __int_as_float(e1.y);
        float v2 = __int_as_float(e2.y), v3 = __int_as_float(e3.y);
        float2 a0 = __half22float2(*(__half2*)&u0.x), b0 = __half22float2(*(__half2*)&u0.y);
        float2 a1 = __half22float2(*(__half2*)&u1.x), b1 = __half22float2(*(__half2*)&u1.y);
        float2 a2 = __half22float2(*(__half2*)&u2.x), b2 = __half22float2(*(__half2*)&u2.y);
        float2 a3 = __half22float2(*(__half2*)&u3.x), b3 = __half22float2(*(__half2*)&u3.y);
        acc.x += a0.x * v0 + a1.x * v1 + a2.x * v2 + a3.x * v3;
        acc.y += a0.y * v0 + a1.y * v1 + a2.y * v2 + a3.y * v3;
        acc.z += b0.x * v0 + b1.x * v1 + b2.x * v2 + b3.x * v3;
        acc.w += b0.y * v0 + b1.y * v1 + b2.y * v2 + b3.y * v3;
    }
    for (; t < e; t++) {
        int2 e0 = ei[t];
        float v0 = __int_as_float(e0.y);
        uint2 u0 = srcH[(size_t)e0.x * 32 + lane];
        float2 a0 = __half22float2(*(__half2*)&u0.x), b0 = __half22float2(*(__half2*)&u0.y);
        acc.x += a0.x * v0; acc.y += a0.y * v0;
        acc.z += b0.x * v0; acc.w += b0.y * v0;
    }
    dstH[(size_t)seg * 32 + lane] = pack_f4(acc);
}

// ---------------- weight prep: gate-grouped cat matrices, fp16 ----------------
__global__ void k_wprep_all(
    const float* __restrict__ p0ih, const float* __restrict__ p0hh,
    const float* __restrict__ e0ih, const float* __restrict__ e0hh,
    const float* __restrict__ p1ih, const float* __restrict__ p1hh,
    const float* __restrict__ e1ih, const float* __restrict__ e1hh) {
    int slot = blockIdx.x >> 9;
    int wrow = blockIdx.x & 511;
    int p = threadIdx.x;
    const float* Wih;
    const float* Whh;
    switch (slot) {
        case 0: Wih = p0ih; Whh = p0hh; break;
        case 1: Wih = e0ih; Whh = e0hh; break;
        case 2: Wih = p1ih; Whh = p1hh; break;
        default: Wih = e1ih; Whh = e1hh; break;
    }
    int gy = wrow >> 8, rem = wrow & 255;
    int g = rem >> 6, j = rem & 63;
    int gc = gy * 64 + j;
    int k0 = 2 * p, k1 = 2 * p + 1;
    float v0 = 0.f, v1 = 0.f;
    if (g == 0 || g == 1) {
        int row = g * 128 + gc;
        v0 = (k0 < 128) ? Wih[row * 128 + k0] : Whh[row * 128 + (k0 - 128)];
        v1 = (k1 < 128) ? Wih[row * 128 + k1] : Whh[row * 128 + (k1 - 128)];
    } else if (g == 2) {
        int row = 256 + gc;
        if (k0 < 128) v0 = Wih[row * 128 + k0];
        if (k1 < 128) v1 = Wih[row * 128 + k1];
    } else {
        int row = 256 + gc;
        if (k0 >= 128) v0 = Whh[row * 128 + (k0 - 128)];
        if (k1 >= 128) v1 = Whh[row * 128 + (k1 - 128)];
    }
    d_wcat3[slot * 65536 + wrow * 128 + p] = pack_h2(v0, v1);
}

// ---------------- GRU v3: 128 rows x 64 gate-cols per block ----------------
#define GRU3_BUF_U32 6400
#define GRU3_SMEM    51200

__device__ __forceinline__ void gru3_loadA(uint32_t sbase, int bsel,
        const uint2* msgH, const float4* h4, int c, int m0, int M, int tid) {
    #pragma unroll
    for (int i = 0; i < 2; i++) {
        int id = tid + i * 512;
        int r = id >> 3, j = id & 7;
        int grow = m0 + r;
        uint32_t h0 = 0, h1 = 0;
        if (c < 4) {
            if (grow < M) {
                uint2 u = msgH[(size_t)grow * 32 + (c & 3) * 8 + j];
                h0 = u.x; h1 = u.y;
            }
        } else {
            float4 v = make_float4(0.f, 0.f, 0.f, 0.f);
            if (grow < M) v = h4[(size_t)grow * 32 + (c & 3) * 8 + j];
            h0 = pack_h2(v.x, v.y); h1 = pack_h2(v.z, v.w);
        }
        uint32_t dst = sbase + (uint32_t)(bsel * GRU3_BUF_U32 + r * 20 + 2 * j) * 4;
        asm volatile("st.shared.v2.b32 [%0], {%1,%2};" :: "r"(dst), "r"(h0), "r"(h1));
    }
}

__device__ __forceinline__ void gru3_loadB(uint32_t sbase, int bsel,
        const uint4* w16, int c, int gy, int tid) {
    #pragma unroll
    for (int i = 0; i < 2; i++) {
        int id = tid + i * 512;
        if (id < 768) {
            int rp = id >> 2, q = id & 3;
            int blkrow = (c < 4) ? rp : ((rp < 128) ? rp : rp + 64);
            uint32_t dst = sbase +
                (uint32_t)(bsel * GRU3_BUF_U32 + 2560 + rp * 20 + q * 4) * 4;
            const uint4* src = w16 + (size_t)(gy * 256 + blkrow) * 32 + c * 4 + q;
            asm volatile("cp.async.cg.shared.global [%0], [%1], 16;"
                         :: "r"(dst), "l"(src) : "memory");
        }
    }
    asm volatile("cp.async.commit_group;" ::: "memory");
}

__device__ __forceinline__ void gru3_compute(const uint32_t* dyn, int bsel,
        int rg, int cs, int lane, int c, float acc[16][4]) {
    const uint32_t* A = dyn + bsel * GRU3_BUF_U32;
    const uint32_t* B = A + 2560;
    #pragma unroll
    for (int kt = 0; kt < 2; kt++) {
        int k1 = kt * 8 + (lane & 3);
        #pragma unroll
        for (int rsub = 0; rsub < 2; rsub++) {
            int ar = (rg * 32 + rsub * 16 + (lane >> 2)) * 20 + k1;
            uint32_t a0 = A[ar],     a1 = A[ar + 8 * 20];
            uint32_t a2 = A[ar + 4], a3 = A[ar + 8 * 20 + 4];
            #pragma unroll
            for (int g = 0; g < 4; g++) {
                if (g == 2 && c >= 4) continue;
                if (g == 3 && c < 4) continue;
                #pragma unroll
                for (int ct = 0; ct < 2; ct++) {
                    int local = cs * 16 + ct * 8 + (lane >> 2);
                    int srow = (g < 2) ? g * 64 + local : 128 + local;
                    int br = srow * 20 + k1;
                    uint32_t b0 = B[br], b1 = B[br + 4];
                    MMA_F16(acc[g * 4 + rsub * 2 + ct], a0, a1, a2, a3, b0, b1);
                }
            }
        }
    }
}

__global__ void __launch_bounds__(512, 1)
k_gru3(const uint2* __restrict__ msgH, const float* __restrict__ h_in,
       float* __restrict__ h_out, uint2* __restrict__ hOutH,
       const uint32_t* __restrict__ wcat,
       const float* __restrict__ bih, const float* __restrict__ bhh, int M) {
    extern __shared__ uint32_t dyn[];
    int tid = threadIdx.x;
    int lane = tid & 31, wid = tid >> 5;
    int rg = wid >> 2;
    int cs = wid & 3;
    int m0 = blockIdx.x * 128;
    int gy = blockIdx.y;
    uint32_t sbase = smem_u32(dyn);

    const float4* h4  = (const float4*)h_in;
    const uint4*  w16 = (const uint4*)wcat;

    float acc[16][4];
    #pragma unroll
    for (int t = 0; t < 16; t++)
        #pragma unroll
        for (int i = 0; i < 4; i++) acc[t][i] = 0.f;

    gru3_loadA(sbase, 0, msgH, h4, 0, m0, M, tid);
    gru3_loadB(sbase, 0, w16, 0, gy, tid);

    for (int c = 0; c < 8; c++) {
        if (c < 7) {
            gru3_loadA(sbase, (c + 1) & 1, msgH, h4, c + 1, m0, M, tid);
            gru3_loadB(sbase, (c + 1) & 1, w16, c + 1, gy, tid);
            asm volatile("cp.async.wait_group 1;" ::: "memory");
        } else {
            asm volatile("cp.async.wait_group 0;" ::: "memory");
        }
        __syncthreads();
        gru3_compute(dyn, c & 1, rg, cs, lane, c, acc);
        __syncthreads();
    }

    // stage h_in block cols into smem (coalesced), stride 68
    float* hs = (float*)dyn;
    #pragma unroll
    for (int i = 0; i < 4; i++) {
        int id = tid + i * 512;
        int r = id >> 4, f = id & 15;
        int row = m0 + r;
        float4 v = make_float4(0.f, 0.f, 0.f, 0.f);
        if (row < M) v = h4[(size_t)row * 32 + gy * 16 + f];
        *(float4*)(hs + r * 68 + f * 4) = v;
    }
    __syncthreads();

    // in-register gate, result into hs
    #pragma unroll
    for (int rsub = 0; rsub < 2; rsub++) {
        #pragma unroll
        for (int ct = 0; ct < 2; ct++) {
            #pragma unroll
            for (int i = 0; i < 4; i++) {
                int row_l = rg * 32 + rsub * 16 + (lane >> 2) + (i >> 1) * 8;
                int col_l = cs * 16 + ct * 8 + (lane & 3) * 2 + (i & 1);
                int gcol = gy * 64 + col_l;
                float Sr = acc[0 + rsub * 2 + ct][i];
                float Sz = acc[4 + rsub * 2 + ct][i];
                float Xn = acc[8 + rsub * 2 + ct][i];
                float Gn = acc[12 + rsub * 2 + ct][i];
                float r_ = sigmf(Sr + __ldg(bih + gcol) + __ldg(bhh + gcol));
                float z_ = sigmf(Sz + __ldg(bih + 128 + gcol) + __ldg(bhh + 128 + gcol));
                float n_ = tanhf(Xn + __ldg(bih + 256 + gcol) +
                                 r_ * (Gn + __ldg(bhh + 256 + gcol)));
                float hv = hs[row_l * 68 + col_l];
                hs[row_l * 68 + col_l] = (1.f - z_) * n_ + z_ * hv;
            }
        }
    }
    __syncthreads();

    // coalesced writeout (fp32 + optional fp16 copy)
    #pragma unroll
    for (int i = 0; i < 4; i++) {
        int id = tid + i * 512;
        int r = id >> 4, f = id & 15;
        int row = m0 + r;
        if (row < M) {
            float4 v = *(float4*)(hs + r * 68 + f * 4);
            ((float4*)h_out)[(size_t)row * 32 + gy * 16 + f] = v;
            if (hOutH)
                hOutH[(size_t)row * 32 + gy * 16 + f] = pack_f4(v);
        }
    }
}

// ---------------- final FC: 64 rows/block, dynamic smem ----------------
#define FC_SMEM_FLOATS (128 * 33 + 64 * 128)

__global__ void __launch_bounds__(256)
k_fc(const float* __restrict__ es, const float* __restrict__ fcw,
     const float* __restrict__ fcb, float* __restrict__ logits) {
    extern __shared__ float sf[];
    float* Wt = sf;
    float* rowbuf = sf + 128 * 33;
    int tid = threadIdx.x;
    #pragma unroll
    for (int i = 0; i < 4; i++) {
        int idx = tid + i * 256;
        int j = idx >> 5, k4 = idx & 31;
        float4 w = ((const float4*)fcw)[j * 32 + k4];
        Wt[(k4 * 4 + 0) * 33 + j] = w.x; Wt[(k4 * 4 + 1) * 33 + j] = w.y;
        Wt[(k4 * 4 + 2) * 33 + j] = w.z; Wt[(k4 * 4 + 3) * 33 + j] = w.w;
    }
    int base = blockIdx.x * 64;
    #pragma unroll
    for (int i = 0; i < 8; i++) {
        int id = tid + i * 256;
        int r = id >> 5, f4 = id & 31;
        ((float4*)(rowbuf + r * 128))[f4] =
            ((const float4*)(es + (size_t)(base + r) * 128))[f4];
    }
    __syncthreads();
    int w = tid >> 5, lane = tid & 31;
    float acc[8];
    float b = fcb[lane];
    #pragma unroll
    for (int r = 0; r < 8; r++) acc[r] = b;
    for (int k = 0; k < 128; k++) {
        float wt = Wt[k * 33 + lane];
        #pragma unroll
        for (int r = 0; r < 8; r++)
            acc[r] += rowbuf[(w * 8 + r) * 128 + k] * wt;
    }
    #pragma unroll
    for (int r = 0; r < 8; r++)
        logits[(size_t)(base + w * 8 + r) * Cn + lane] = acc[r];
}

// ---------------- host orchestration ----------------
extern "C" void kernel_launch(void* const* d_in, const int* in_sizes, int n_in,
                              void* d_out, int out_size) {
    (void)in_sizes; (void)n_in; (void)out_size;
    const int*   seed_index = (const int*)d_in[0];
    const float* es_in  = (const float*)d_in[1];
    const float* ps_in  = (const float*)d_in[2];
    const int*   rows   = (const int*)d_in[3];
    const int*   cols   = (const int*)d_in[4];
    const float* vals   = (const float*)d_in[5];
    const float* fcw    = (const float*)d_in[22];
    const float* fcb    = (const float*)d_in[23];

    float* out       = (float*)d_out;
    float* out_logit = out;
    float* out_es    = out + (size_t)En * Cn;
    float* out_ps    = out_es + (size_t)En * Dn;

    cudaFuncSetAttribute(k_gru3, cudaFuncAttributeMaxDynamicSharedMemorySize, GRU3_SMEM);
    cudaFuncSetAttribute(k_fc, cudaFuncAttributeMaxDynamicSharedMemorySize,
                         FC_SMEM_FLOATS * 4);

    void *pOffP, *pOffE, *pEiP, *pEiE, *pPmsgH, *pEmsgH, *pWcat, *pEsB, *pPsB, *pPsH;
    cudaGetSymbolAddress(&pOffP, d_offP);
    cudaGetSymbolAddress(&pOffE, d_offE);
    cudaGetSymbolAddress(&pEiP, d_eiP);
    cudaGetSymbolAddress(&pEiE, d_eiE);
    cudaGetSymbolAddress(&pPmsgH, d_pmsgH);
    cudaGetSymbolAddress(&pEmsgH, d_emsgH);
    cudaGetSymbolAddress(&pWcat, d_wcat3);
    cudaGetSymbolAddress(&pEsB, d_esB);
    cudaGetSymbolAddress(&pPsB, d_psB);
    cudaGetSymbolAddress(&pPsH, d_psH);

    // CSR build
    k_zero_counts<<<(En + 255) / 256, 256>>>();
    k_count<<<(NNZn + 255) / 256, 256>>>(rows, cols);
    k_scan1<<<NBP + NBE, 1024>>>();
    k_scan2<<<2, 1024>>>();
    k_scan3<<<NBP + NBE, 1024>>>();
    k_fill<<<(NNZn + 255) / 256, 256>>>(rows, cols, vals);

    // all 4 GRU weight matrices (slots: l0_p, l0_e, l1_p, l1_e)
    k_wprep_all<<<2048, 128>>>(
        (const float*)d_in[10], (const float*)d_in[11],   // l0 p
        (const float*)d_in[6],  (const float*)d_in[7],    // l0 e
        (const float*)d_in[18], (const float*)d_in[19],   // l1 p
        (const float*)d_in[14], (const float*)d_in[15]);  // l1 e

    dim3 spmmB(32, 8);
    dim3 gE((En + 127) / 128, 2);
    dim3 gP((Pn + 127) / 128, 2);

    for (int l = 0; l < 2; l++) {
        const float* ebih = (const float*)d_in[6 + l * 8 + 2];
        const float* ebhh = (const float*)d_in[6 + l * 8 + 3];
        const float* pbih = (const float*)d_in[6 + l * 8 + 6];
        const float* pbhh = (const float*)d_in[6 + l * 8 + 7];

        const float* es_cur = (l == 0) ? es_in : (const float*)pEsB;
        const float* ps_cur = (l == 0) ? ps_in : (const float*)pPsB;
        float* es_nxt = (l == 0) ? (float*)pEsB : out_es;
        float* ps_nxt = (l == 0) ? (float*)pPsB : out_ps;

        const uint32_t* wP = (const uint32_t*)pWcat + (l * 2 + 0) * 65536;
        const uint32_t* wE = (const uint32_t*)pWcat + (l * 2 + 1) * 65536;

        k_seed_mean<<<1, dim3(128, 8)>>>(es_cur, seed_index);

        // p_msg (fp16) = segment_sum(es[row]*w); ps = GRU(p_msg, ps); also emit psH fp16
        k_spmm_f32<<<(Pn + 7) / 8, spmmB>>>((const float4*)es_cur, (uint2*)pPmsgH,
                                            (const int*)pOffP, (const int2*)pEiP, Pn);
        k_gru3<<<gP, 512, GRU3_SMEM>>>((const uint2*)pPmsgH, ps_cur, ps_nxt,
                                       (uint2*)pPsH, wP, pbih, pbhh, Pn);

        // e_msg (fp16) = segment_sum(psH[col]*w) + smean; es = GRU(e_msg, es)
        k_spmm_h16<<<(En + 7) / 8, spmmB>>>((const uint2*)pPsH, (uint2*)pEmsgH,
                                            (const int*)pOffE, (const int2*)pEiE, En);
        k_gru3<<<gE, 512, GRU3_SMEM>>>((const uint2*)pEmsgH, es_cur, es_nxt,
                                       (uint2*)0, wE, ebih, ebhh, En);
    }

    k_fc<<<En / 64, 256, FC_SMEM_FLOATS * 4>>>(out_es, fcw, fcb, out_logit);
}

// round 13
// speedup vs baseline: 1.0378x; 1.0378x over previous
#include <cuda_runtime.h>
#include <cuda_fp16.h>
#include <math.h>
#include <stdint.h>

#define En     200000
#define Pn     50000
#define Dn     128
#define NNZn   2000000
#define Cn     32
#define NSEEDn 320
#define G3     384   // 3*D

// ---------------- scratch (device globals; no allocation allowed) ----------------
__device__ float d_pmsg[(size_t)Pn * Dn];
__device__ float d_emsg[(size_t)En * Dn];
__device__ uint2 d_psH[(size_t)Pn * 32];    // fp16 copy of ps (E-side gather source)
__device__ float d_esB[(size_t)En * Dn];    // ping-pong for es
__device__ float d_psB[(size_t)Pn * Dn];    // ping-pong for ps
__device__ int   d_cntP[Pn];
__device__ int   d_offP[Pn + 1];
__device__ int   d_curP[Pn];
__device__ int   d_cntE[En];
__device__ int   d_offE[En + 1];
__device__ int   d_curE[En];
__device__ int2  d_eiP[NNZn];
__device__ int2  d_eiE[NNZn];
__device__ float d_smean[Dn];
__device__ int   d_partP[64];
__device__ int   d_partE[256];
// fp16 gate-grouped cat weights, 4 slots (l0_p, l0_e, l1_p, l1_e)
__device__ uint32_t d_wcat3[4 * 512 * 128];

#define NBP ((Pn + 1023) / 1024)   // 49
#define NBE ((En + 1023) / 1024)   // 196

// ---------------- helpers ----------------
__device__ __forceinline__ uint32_t smem_u32(const void* p) {
    uint32_t a;
    asm("{ .reg .u64 t; cvta.to.shared.u64 t, %1; cvt.u32.u64 %0, t; }" : "=r"(a) : "l"(p));
    return a;
}
__device__ __forceinline__ float sigmf(float x) { return 1.f / (1.f + expf(-x)); }
__device__ __forceinline__ uint32_t pack_h2(float a, float b) {
    __half2 h = __floats2half2_rn(a, b);
    return *(uint32_t*)&h;
}
__device__ __forceinline__ uint2 pack_f4(float4 v) {
    uint2 o;
    o.x = pack_h2(v.x, v.y);
    o.y = pack_h2(v.z, v.w);
    return o;
}

#define MMA_F16(acc, a0, a1, a2, a3, b0, b1)                                \
    asm volatile("mma.sync.aligned.m16n8k16.row.col.f32.f16.f16.f32 "       \
                 "{%0,%1,%2,%3}, {%4,%5,%6,%7}, {%8,%9}, {%0,%1,%2,%3};"    \
                 : "+f"(acc[0]), "+f"(acc[1]), "+f"(acc[2]), "+f"(acc[3])   \
                 : "r"(a0), "r"(a1), "r"(a2), "r"(a3), "r"(b0), "r"(b1));

// ---------------- CSR build ----------------
__global__ void k_zero_counts() {
    int i = blockIdx.x * blockDim.x + threadIdx.x;
    if (i < En) d_cntE[i] = 0;
    if (i < Pn) d_cntP[i] = 0;
}

__global__ void k_count(const int* __restrict__ rows, const int* __restrict__ cols) {
    int i = blockIdx.x * blockDim.x + threadIdx.x;
    if (i < NNZn) {
        atomicAdd(&d_cntE[rows[i]], 1);
        atomicAdd(&d_cntP[cols[i]], 1);
    }
}

__global__ void k_scan1() {
    __shared__ int s[1024];
    int isE = (blockIdx.x >= NBP);
    int b = isE ? blockIdx.x - NBP : blockIdx.x;
    const int* cnt = isE ? d_cntE : d_cntP;
    int* off = isE ? d_offE : d_offP;
    int* part = isE ? d_partE : d_partP;
    int n = isE ? En : Pn;
    int g = b * 1024 + threadIdx.x;
    s[threadIdx.x] = (g < n) ? cnt[g] : 0;
    __syncthreads();
    for (int o = 1; o < 1024; o <<= 1) {
        int t = (threadIdx.x >= o) ? s[threadIdx.x - o] : 0;
        __syncthreads();
        s[threadIdx.x] += t;
        __syncthreads();
    }
    if (g < n) off[g + 1] = s[threadIdx.x];
    if (threadIdx.x == 1023) part[b] = s[1023];
    if (g == 0) off[0] = 0;
}

__global__ void k_scan2() {
    __shared__ int s[1024];
    int isE = (blockIdx.x == 1);
    int* part = isE ? d_partE : d_partP;
    int n = isE ? NBE : NBP;
    s[threadIdx.x] = (threadIdx.x < n) ? part[threadIdx.x] : 0;
    __syncthreads();
    for (int o = 1; o < 1024; o <<= 1) {
        int t = (threadIdx.x >= o) ? s[threadIdx.x - o] : 0;
        __syncthreads();
        s[threadIdx.x] += t;
        __syncthreads();
    }
    if (threadIdx.x < n)
        part[threadIdx.x] = (threadIdx.x == 0) ? 0 : s[threadIdx.x - 1];
}

__global__ void k_scan3() {
    int isE = (blockIdx.x >= NBP);
    int b = isE ? blockIdx.x - NBP : blockIdx.x;
    int* off = isE ? d_offE : d_offP;
    int* cur = isE ? d_curE : d_curP;
    const int* part = isE ? d_partE : d_partP;
    int n = isE ? En : Pn;
    int g = b * 1024 + threadIdx.x;
    if (g < n) {
        int v = off[g + 1] + part[b];
        off[g + 1] = v;
        if (g + 1 < n) cur[g + 1] = v;
    }
    if (g == 0) cur[0] = 0;
}

__global__ void k_fill(const int* __restrict__ rows, const int* __restrict__ cols,
                       const float* __restrict__ vals) {
    int i = blockIdx.x * blockDim.x + threadIdx.x;
    if (i < NNZn) {
        int r = rows[i], c = cols[i];
        int vb = __float_as_int(vals[i]);
        int pp = atomicAdd(&d_curP[c], 1);
        d_eiP[pp] = make_int2(r, vb);
        int pe = atomicAdd(&d_curE[r], 1);
        d_eiE[pe] = make_int2(c, vb);
    }
}

// ---------------- seed mean ----------------
__global__ void k_seed_mean(const float* __restrict__ es, const int* __restrict__ sidx) {
    __shared__ float red[8][128];
    int d = threadIdx.x, ty = threadIdx.y;
    float s = 0.f;
    for (int i = ty; i < NSEEDn; i += 8)
        s += es[(size_t)sidx[i] * Dn + d];
    red[ty][d] = s;
    __syncthreads();
    if (ty == 0) {
        float tot = 0.f;
        #pragma unroll
        for (int j = 0; j < 8; j++) tot += red[j][d];
        d_smean[d] = tot * (1.f / NSEEDn);
    }
}

// ---------------- SpMM P-side: fp32 gather (es), fp32 msg out ----------------
__global__ void k_spmm(const float4* __restrict__ src, float4* __restrict__ dst,
                       const int* __restrict__ off, const int2* __restrict__ ei,
                       int nseg) {
    int seg = blockIdx.x * 8 + threadIdx.y;
    if (seg >= nseg) return;
    int lane = threadIdx.x;
    float4 acc = make_float4(0.f, 0.f, 0.f, 0.f);
    int b = off[seg], e = off[seg + 1];
    int t = b;
    for (; t + 4 <= e; t += 4) {
        int2 e0 = ei[t], e1 = ei[t + 1], e2 = ei[t + 2], e3 = ei[t + 3];
        float4 x0 = src[(size_t)e0.x * 32 + lane];
        float4 x1 = src[(size_t)e1.x * 32 + lane];
        float4 x2 = src[(size_t)e2.x * 32 + lane];
        float4 x3 = src[(size_t)e3.x * 32 + lane];
        float v0 = __int_as_float(e0.y), v1 = __int_as_float(e1.y);
        float v2 = __int_as_float(e2.y), v3 = __int_as_float(e3.y);
        acc.x += x0.x * v0 + x1.x * v1 + x2.x * v2 + x3.x * v3;
        acc.y += x0.y * v0 + x1.y * v1 + x2.y * v2 + x3.y * v3;
        acc.z += x0.z * v0 + x1.z * v1 + x2.z * v2 + x3.z * v3;
        acc.w += x0.w * v0 + x1.w * v1 + x2.w * v2 + x3.w * v3;
    }
    for (; t < e; t++) {
        int2 e0 = ei[t];
        float v0 = __int_as_float(e0.y);
        float4 x0 = src[(size_t)e0.x * 32 + lane];
        acc.x += x0.x * v0; acc.y += x0.y * v0;
        acc.z += x0.z * v0; acc.w += x0.w * v0;
    }
    dst[(size_t)seg * 32 + lane] = acc;
}

// ---------------- SpMM E-side: fp16 gather (psH), +smean, fp32 msg out ----------------
__global__ void k_spmm_h16(const uint2* __restrict__ srcH, float4* __restrict__ dst,
                           const int* __restrict__ off, const int2* __restrict__ ei,
                           int nseg) {
    int seg = blockIdx.x * 8 + threadIdx.y;
    if (seg >= nseg) return;
    int lane = threadIdx.x;
    float4 acc = ((const float4*)d_smean)[lane];
    int b = off[seg], e = off[seg + 1];
    int t = b;
    for (; t + 4 <= e; t += 4) {
        int2 e0 = ei[t], e1 = ei[t + 1], e2 = ei[t + 2], e3 = ei[t + 3];
        uint2 u0 = srcH[(size_t)e0.x * 32 + lane];
        uint2 u1 = srcH[(size_t)e1.x * 32 + lane];
        uint2 u2 = srcH[(size_t)e2.x * 32 + lane];
        uint2 u3 = srcH[(size_t)e3.x * 32 + lane];
        float v0 = __int_as_float(e0.y), v1 = __int_as_float(e1.y);
        float v2 = __int_as_float(e2.y), v3 = __int_as_float(e3.y);
        float2 a0 = __half22float2(*(__half2*)&u0.x), b0 = __half22float2(*(__half2*)&u0.y);
        float2 a1 = __half22float2(*(__half2*)&u1.x), b1 = __half22float2(*(__half2*)&u1.y);
        float2 a2 = __half22float2(*(__half2*)&u2.x), b2 = __half22float2(*(__half2*)&u2.y);
        float2 a3 = __half22float2(*(__half2*)&u3.x), b3 = __half22float2(*(__half2*)&u3.y);
        acc.x += a0.x * v0 + a1.x * v1 + a2.x * v2 + a3.x * v3;
        acc.y += a0.y * v0 + a1.y * v1 + a2.y * v2 + a3.y * v3;
        acc.z += b0.x * v0 + b1.x * v1 + b2.x * v2 + b3.x * v3;
        acc.w += b0.y * v0 + b1.y * v1 + b2.y * v2 + b3.y * v3;
    }
    for (; t < e; t++) {
        int2 e0 = ei[t];
        float v0 = __int_as_float(e0.y);
        uint2 u0 = srcH[(size_t)e0.x * 32 + lane];
        float2 a0 = __half22float2(*(__half2*)&u0.x), b0 = __half22float2(*(__half2*)&u0.y);
        acc.x += a0.x * v0; acc.y += a0.y * v0;
        acc.z += b0.x * v0; acc.w += b0.y * v0;
    }
    dst[(size_t)seg * 32 + lane] = acc;
}

// ---------------- weight prep: gate-grouped cat matrices, fp16 ----------------
__global__ void k_wprep_all(
    const float* __restrict__ p0ih, const float* __restrict__ p0hh,
    const float* __restrict__ e0ih, const float* __restrict__ e0hh,
    const float* __restrict__ p1ih, const float* __restrict__ p1hh,
    const float* __restrict__ e1ih, const float* __restrict__ e1hh) {
    int slot = blockIdx.x >> 9;
    int wrow = blockIdx.x & 511;
    int p = threadIdx.x;
    const float* Wih;
    const float* Whh;
    switch (slot) {
        case 0: Wih = p0ih; Whh = p0hh; break;
        case 1: Wih = e0ih; Whh = e0hh; break;
        case 2: Wih = p1ih; Whh = p1hh; break;
        default: Wih = e1ih; Whh = e1hh; break;
    }
    int gy = wrow >> 8, rem = wrow & 255;
    int g = rem >> 6, j = rem & 63;
    int gc = gy * 64 + j;
    int k0 = 2 * p, k1 = 2 * p + 1;
    float v0 = 0.f, v1 = 0.f;
    if (g == 0 || g == 1) {
        int row = g * 128 + gc;
        v0 = (k0 < 128) ? Wih[row * 128 + k0] : Whh[row * 128 + (k0 - 128)];
        v1 = (k1 < 128) ? Wih[row * 128 + k1] : Whh[row * 128 + (k1 - 128)];
    } else if (g == 2) {
        int row = 256 + gc;
        if (k0 < 128) v0 = Wih[row * 128 + k0];
        if (k1 < 128) v1 = Wih[row * 128 + k1];
    } else {
        int row = 256 + gc;
        if (k0 >= 128) v0 = Whh[row * 128 + (k0 - 128)];
        if (k1 >= 128) v1 = Whh[row * 128 + (k1 - 128)];
    }
    d_wcat3[slot * 65536 + wrow * 128 + p] = pack_h2(v0, v1);
}

// ---------------- GRU v3: 128 rows x 64 gate-cols per block ----------------
#define GRU3_BUF_U32 6400
#define GRU3_SMEM    51200

__device__ __forceinline__ void gru3_loadA(uint32_t sbase, int bsel,
        const float4* msg4, const float4* h4, int c, int m0, int M, int tid) {
    #pragma unroll
    for (int i = 0; i < 2; i++) {
        int id = tid + i * 512;
        int r = id >> 3, j = id & 7;
        const float4* s4 = (c < 4) ? msg4 : h4;
        int koff = (c & 3) * 8;
        float4 v = make_float4(0.f, 0.f, 0.f, 0.f);
        int grow = m0 + r;
        if (grow < M) v = s4[(size_t)grow * 32 + koff + j];
        uint32_t h0 = pack_h2(v.x, v.y), h1 = pack_h2(v.z, v.w);
        uint32_t dst = sbase + (uint32_t)(bsel * GRU3_BUF_U32 + r * 20 + 2 * j) * 4;
        asm volatile("st.shared.v2.b32 [%0], {%1,%2};" :: "r"(dst), "r"(h0), "r"(h1));
    }
}

__device__ __forceinline__ void gru3_loadB(uint32_t sbase, int bsel,
        const uint4* w16, int c, int gy, int tid) {
    #pragma unroll
    for (int i = 0; i < 2; i++) {
        int id = tid + i * 512;
        if (id < 768) {
            int rp = id >> 2, q = id & 3;
            int blkrow = (c < 4) ? rp : ((rp < 128) ? rp : rp + 64);
            uint32_t dst = sbase +
                (uint32_t)(bsel * GRU3_BUF_U32 + 2560 + rp * 20 + q * 4) * 4;
            const uint4* src = w16 + (size_t)(gy * 256 + blkrow) * 32 + c * 4 + q;
            asm volatile("cp.async.cg.shared.global [%0], [%1], 16;"
                         :: "r"(dst), "l"(src) : "memory");
        }
    }
    asm volatile("cp.async.commit_group;" ::: "memory");
}

__device__ __forceinline__ void gru3_compute(const uint32_t* dyn, int bsel,
        int rg, int cs, int lane, int c, float acc[16][4]) {
    const uint32_t* A = dyn + bsel * GRU3_BUF_U32;
    const uint32_t* B = A + 2560;
    #pragma unroll
    for (int kt = 0; kt < 2; kt++) {
        int k1 = kt * 8 + (lane & 3);
        #pragma unroll
        for (int rsub = 0; rsub < 2; rsub++) {
            int ar = (rg * 32 + rsub * 16 + (lane >> 2)) * 20 + k1;
            uint32_t a0 = A[ar],     a1 = A[ar + 8 * 20];
            uint32_t a2 = A[ar + 4], a3 = A[ar + 8 * 20 + 4];
            #pragma unroll
            for (int g = 0; g < 4; g++) {
                if (g == 2 && c >= 4) continue;
                if (g == 3 && c < 4) continue;
                #pragma unroll
                for (int ct = 0; ct < 2; ct++) {
                    int local = cs * 16 + ct * 8 + (lane >> 2);
                    int srow = (g < 2) ? g * 64 + local : 128 + local;
                    int br = srow * 20 + k1;
                    uint32_t b0 = B[br], b1 = B[br + 4];
                    MMA_F16(acc[g * 4 + rsub * 2 + ct], a0, a1, a2, a3, b0, b1);
                }
            }
        }
    }
}

__global__ void __launch_bounds__(512, 1)
k_gru3(const float* __restrict__ msg, const float* __restrict__ h_in,
       float* __restrict__ h_out, uint2* __restrict__ hOutH,
       const uint32_t* __restrict__ wcat,
       const float* __restrict__ bih, const float* __restrict__ bhh, int M) {
    extern __shared__ uint32_t dyn[];
    int tid = threadIdx.x;
    int lane = tid & 31, wid = tid >> 5;
    int rg = wid >> 2;
    int cs = wid & 3;
    int m0 = blockIdx.x * 128;
    int gy = blockIdx.y;
    uint32_t sbase = smem_u32(dyn);

    const float4* msg4 = (const float4*)msg;
    const float4* h4   = (const float4*)h_in;
    const uint4*  w16  = (const uint4*)wcat;

    float acc[16][4];
    #pragma unroll
    for (int t = 0; t < 16; t++)
        #pragma unroll
        for (int i = 0; i < 4; i++) acc[t][i] = 0.f;

    gru3_loadA(sbase, 0, msg4, h4, 0, m0, M, tid);
    gru3_loadB(sbase, 0, w16, 0, gy, tid);

    for (int c = 0; c < 8; c++) {
        if (c < 7) {
            gru3_loadA(sbase, (c + 1) & 1, msg4, h4, c + 1, m0, M, tid);
            gru3_loadB(sbase, (c + 1) & 1, w16, c + 1, gy, tid);
            asm volatile("cp.async.wait_group 1;" ::: "memory");
        } else {
            asm volatile("cp.async.wait_group 0;" ::: "memory");
        }
        __syncthreads();
        gru3_compute(dyn, c & 1, rg, cs, lane, c, acc);
        __syncthreads();
    }

    // stage h_in block cols into smem (coalesced), stride 68
    float* hs = (float*)dyn;
    #pragma unroll
    for (int i = 0; i < 4; i++) {
        int id = tid + i * 512;
        int r = id >> 4, f = id & 15;
        int row = m0 + r;
        float4 v = make_float4(0.f, 0.f, 0.f, 0.f);
        if (row < M) v = h4[(size_t)row * 32 + gy * 16 + f];
        *(float4*)(hs + r * 68 + f * 4) = v;
    }
    __syncthreads();

    // in-register gate, result into hs
    #pragma unroll
    for (int rsub = 0; rsub < 2; rsub++) {
        #pragma unroll
        for (int ct = 0; ct < 2; ct++) {
            #pragma unroll
            for (int i = 0; i < 4; i++) {
                int row_l = rg * 32 + rsub * 16 + (lane >> 2) + (i >> 1) * 8;
                int col_l = cs * 16 + ct * 8 + (lane & 3) * 2 + (i & 1);
                int gcol = gy * 64 + col_l;
                float Sr = acc[0 + rsub * 2 + ct][i];
                float Sz = acc[4 + rsub * 2 + ct][i];
                float Xn = acc[8 + rsub * 2 + ct][i];
                float Gn = acc[12 + rsub * 2 + ct][i];
                float r_ = sigmf(Sr + __ldg(bih + gcol) + __ldg(bhh + gcol));
                float z_ = sigmf(Sz + __ldg(bih + 128 + gcol) + __ldg(bhh + 128 + gcol));
                float n_ = tanhf(Xn + __ldg(bih + 256 + gcol) +
                                 r_ * (Gn + __ldg(bhh + 256 + gcol)));
                float hv = hs[row_l * 68 + col_l];
                hs[row_l * 68 + col_l] = (1.f - z_) * n_ + z_ * hv;
            }
        }
    }
    __syncthreads();

    // coalesced writeout (fp32 + optional fp16 copy)
    #pragma unroll
    for (int i = 0; i < 4; i++) {
        int id = tid + i * 512;
        int r = id >> 4, f = id & 15;
        int row = m0 + r;
        if (row < M) {
            float4 v = *(float4*)(hs + r * 68 + f * 4);
            ((float4*)h_out)[(size_t)row * 32 + gy * 16 + f] = v;
            if (hOutH)
                hOutH[(size_t)row * 32 + gy * 16 + f] = pack_f4(v);
        }
    }
}

// ---------------- final FC: 64 rows/block, dynamic smem ----------------
#define FC_SMEM_FLOATS (128 * 33 + 64 * 128)

__global__ void __launch_bounds__(256)
k_fc(const float* __restrict__ es, const float* __restrict__ fcw,
     const float* __restrict__ fcb, float* __restrict__ logits) {
    extern __shared__ float sf[];
    float* Wt = sf;
    float* rowbuf = sf + 128 * 33;
    int tid = threadIdx.x;
    #pragma unroll
    for (int i = 0; i < 4; i++) {
        int idx = tid + i * 256;
        int j = idx >> 5, k4 = idx & 31;
        float4 w = ((const float4*)fcw)[j * 32 + k4];
        Wt[(k4 * 4 + 0) * 33 + j] = w.x; Wt[(k4 * 4 + 1) * 33 + j] = w.y;
        Wt[(k4 * 4 + 2) * 33 + j] = w.z; Wt[(k4 * 4 + 3) * 33 + j] = w.w;
    }
    int base = blockIdx.x * 64;
    #pragma unroll
    for (int i = 0; i < 8; i++) {
        int id = tid + i * 256;
        int r = id >> 5, f4 = id & 31;
        ((float4*)(rowbuf + r * 128))[f4] =
            ((const float4*)(es + (size_t)(base + r) * 128))[f4];
    }
    __syncthreads();
    int w = tid >> 5, lane = tid & 31;
    float acc[8];
    float b = fcb[lane];
    #pragma unroll
    for (int r = 0; r < 8; r++) acc[r] = b;
    for (int k = 0; k < 128; k++) {
        float wt = Wt[k * 33 + lane];
        #pragma unroll
        for (int r = 0; r < 8; r++)
            acc[r] += rowbuf[(w * 8 + r) * 128 + k] * wt;
    }
    #pragma unroll
    for (int r = 0; r < 8; r++)
        logits[(size_t)(base + w * 8 + r) * Cn + lane] = acc[r];
}

// ---------------- host orchestration ----------------
extern "C" void kernel_launch(void* const* d_in, const int* in_sizes, int n_in,
                              void* d_out, int out_size) {
    (void)in_sizes; (void)n_in; (void)out_size;
    const int*   seed_index = (const int*)d_in[0];
    const float* es_in  = (const float*)d_in[1];
    const float* ps_in  = (const float*)d_in[2];
    const int*   rows   = (const int*)d_in[3];
    const int*   cols   = (const int*)d_in[4];
    const float* vals   = (const float*)d_in[5];
    const float* fcw    = (const float*)d_in[22];
    const float* fcb    = (const float*)d_in[23];

    float* out       = (float*)d_out;
    float* out_logit = out;
    float* out_es    = out + (size_t)En * Cn;
    float* out_ps    = out_es + (size_t)En * Dn;

    cudaFuncSetAttribute(k_gru3, cudaFuncAttributeMaxDynamicSharedMemorySize, GRU3_SMEM);
    cudaFuncSetAttribute(k_fc, cudaFuncAttributeMaxDynamicSharedMemorySize,
                         FC_SMEM_FLOATS * 4);

    void *pOffP, *pOffE, *pEiP, *pEiE, *pPmsg, *pEmsg, *pWcat, *pEsB, *pPsB, *pPsH;
    cudaGetSymbolAddress(&pOffP, d_offP);
    cudaGetSymbolAddress(&pOffE, d_offE);
    cudaGetSymbolAddress(&pEiP, d_eiP);
    cudaGetSymbolAddress(&pEiE, d_eiE);
    cudaGetSymbolAddress(&pPmsg, d_pmsg);
    cudaGetSymbolAddress(&pEmsg, d_emsg);
    cudaGetSymbolAddress(&pWcat, d_wcat3);
    cudaGetSymbolAddress(&pEsB, d_esB);
    cudaGetSymbolAddress(&pPsB, d_psB);
    cudaGetSymbolAddress(&pPsH, d_psH);

    // CSR build
    k_zero_counts<<<(En + 255) / 256, 256>>>();
    k_count<<<(NNZn + 255) / 256, 256>>>(rows, cols);
    k_scan1<<<NBP + NBE, 1024>>>();
    k_scan2<<<2, 1024>>>();
    k_scan3<<<NBP + NBE, 1024>>>();
    k_fill<<<(NNZn + 255) / 256, 256>>>(rows, cols, vals);

    // all 4 GRU weight matrices (slots: l0_p, l0_e, l1_p, l1_e)
    k_wprep_all<<<2048, 128>>>(
        (const float*)d_in[10], (const float*)d_in[11],   // l0 p
        (const float*)d_in[6],  (const float*)d_in[7],    // l0 e
        (const float*)d_in[18], (const float*)d_in[19],   // l1 p
        (const float*)d_in[14], (const float*)d_in[15]);  // l1 e

    dim3 spmmB(32, 8);
    dim3 gE((En + 127) / 128, 2);
    dim3 gP((Pn + 127) / 128, 2);

    for (int l = 0; l < 2; l++) {
        const float* ebih = (const float*)d_in[6 + l * 8 + 2];
        const float* ebhh = (const float*)d_in[6 + l * 8 + 3];
        const float* pbih = (const float*)d_in[6 + l * 8 + 6];
        const float* pbhh = (const float*)d_in[6 + l * 8 + 7];

        const float* es_cur = (l == 0) ? es_in : (const float*)pEsB;
        const float* ps_cur = (l == 0) ? ps_in : (const float*)pPsB;
        float* es_nxt = (l == 0) ? (float*)pEsB : out_es;
        float* ps_nxt = (l == 0) ? (float*)pPsB : out_ps;

        const uint32_t* wP = (const uint32_t*)pWcat + (l * 2 + 0) * 65536;
        const uint32_t* wE = (const uint32_t*)pWcat + (l * 2 + 1) * 65536;

        k_seed_mean<<<1, dim3(128, 8)>>>(es_cur, seed_index);

        // p_msg = segment_sum(es[row]*w); ps = GRU(p_msg, ps); also emit psH fp16
        k_spmm<<<(Pn + 7) / 8, spmmB>>>((const float4*)es_cur, (float4*)pPmsg,
                                        (const int*)pOffP, (const int2*)pEiP, Pn);
        k_gru3<<<gP, 512, GRU3_SMEM>>>((const float*)pPmsg, ps_cur, ps_nxt,
                                       (uint2*)pPsH, wP, pbih, pbhh, Pn);

        // e_msg = segment_sum(psH[col]*w) + smean (fp16 gather); es = GRU(e_msg, es)
        k_spmm_h16<<<(En + 7) / 8, spmmB>>>((const uint2*)pPsH, (float4*)pEmsg,
                                            (const int*)pOffE, (const int2*)pEiE, En);
        k_gru3<<<gE, 512, GRU3_SMEM>>>((const float*)pEmsg, es_cur, es_nxt,
                                       (uint2*)0, wE, ebih, ebhh, En);
    }

    k_fc<<<En / 64, 256, FC_SMEM_FLOATS * 4>>>(out_es, fcw, fcb, out_logit);
}